// round 17
// baseline (speedup 1.0000x reference)
#include <cuda_runtime.h>
#include <cuda_bf16.h>
#include <math.h>

#define S    2048
#define NH   32
#define HD   128
#define HID  4096
#define NEGV -1000000000.0f
#define HHSZ 204
#define RECENT 204
#define SEL  (S - RECENT)
#define NKEEP 408
#define NKP   416

typedef __nv_bfloat16 bf16;

// ---------------- scratch ----------------------------------------------------
__device__ float g_q[(size_t)S * HID];
__device__ float g_k[(size_t)S * HID];
__device__ float g_scores[(size_t)NH * S * S];
__device__ float g_hh[NH * S];
__device__ float g_hhpart[8 * NH * S];
__device__ float g_mask[NH * S];
__device__ float g_pdiag[NH * S];
__device__ int   g_idx[NH * NKP];

__device__ bf16 g_hs_b[(size_t)S * HID],  g_hs_s[(size_t)S * HID];
__device__ bf16 g_w_b[4][(size_t)HID * HID], g_w_s[4][(size_t)HID * HID];
__device__ bf16 g_qb[(size_t)S * HID], g_qs[(size_t)S * HID];
__device__ bf16 g_kb[(size_t)S * HID], g_ks[(size_t)S * HID];
__device__ bf16 g_vb[(size_t)S * HID], g_vs[(size_t)S * HID];
__device__ bf16 g_pcb[(size_t)NH * S * NKP], g_pcs[(size_t)NH * S * NKP];
__device__ bf16 g_vcb[(size_t)NH * NKP * HD], g_vcs[(size_t)NH * NKP * HD];
__device__ bf16 g_ab[(size_t)S * HID], g_as[(size_t)S * HID];

// ---------------- HMMA helpers (proven) --------------------------------------
__device__ __forceinline__ void mma_bf16(float c[4],
    unsigned a0, unsigned a1, unsigned a2, unsigned a3, unsigned b0, unsigned b1)
{
    asm volatile(
        "mma.sync.aligned.m16n8k16.row.col.f32.bf16.bf16.f32 "
        "{%0,%1,%2,%3}, {%4,%5,%6,%7}, {%8,%9}, {%0,%1,%2,%3};"
        : "+f"(c[0]), "+f"(c[1]), "+f"(c[2]), "+f"(c[3])
        : "r"(a0), "r"(a1), "r"(a2), "r"(a3), "r"(b0), "r"(b1));
}
__device__ __forceinline__ void ldsm_x4(unsigned r[4], unsigned addr)
{
    asm volatile("ldmatrix.sync.aligned.m8n8.x4.shared.b16 {%0,%1,%2,%3}, [%4];"
        : "=r"(r[0]), "=r"(r[1]), "=r"(r[2]), "=r"(r[3]) : "r"(addr));
}
__device__ __forceinline__ void ldsm_x4t(unsigned r[4], unsigned addr)
{
    asm volatile("ldmatrix.sync.aligned.m8n8.x4.trans.shared.b16 {%0,%1,%2,%3}, [%4];"
        : "=r"(r[0]), "=r"(r[1]), "=r"(r[2]), "=r"(r[3]) : "r"(addr));
}
__device__ __forceinline__ void cp16(unsigned dst, const void* src)
{
    asm volatile("cp.async.cg.shared.global [%0], [%1], 16;" :: "r"(dst), "l"(src));
}
__device__ __forceinline__ void cp_commit() { asm volatile("cp.async.commit_group;" ::: "memory"); }
__device__ __forceinline__ void cp_wait0() { asm volatile("cp.async.wait_group 0;" ::: "memory"); }

#define MMA_NJ_BLOCK(accA, accB, accA2, accB2, abf, asf, bbf, bsf) do { \
    mma_bf16(accA,  (abf)[0][0], (abf)[0][1], (abf)[0][2], (abf)[0][3], (bsf)[0], (bsf)[1]); \
    mma_bf16(accB,  (abf)[0][0], (abf)[0][1], (abf)[0][2], (abf)[0][3], (bsf)[2], (bsf)[3]); \
    mma_bf16(accA2, (abf)[1][0], (abf)[1][1], (abf)[1][2], (abf)[1][3], (bsf)[0], (bsf)[1]); \
    mma_bf16(accB2, (abf)[1][0], (abf)[1][1], (abf)[1][2], (abf)[1][3], (bsf)[2], (bsf)[3]); \
    mma_bf16(accA,  (asf)[0][0], (asf)[0][1], (asf)[0][2], (asf)[0][3], (bbf)[0], (bbf)[1]); \
    mma_bf16(accB,  (asf)[0][0], (asf)[0][1], (asf)[0][2], (asf)[0][3], (bbf)[2], (bbf)[3]); \
    mma_bf16(accA2, (asf)[1][0], (asf)[1][1], (asf)[1][2], (asf)[1][3], (bbf)[0], (bbf)[1]); \
    mma_bf16(accB2, (asf)[1][0], (asf)[1][1], (asf)[1][2], (asf)[1][3], (bbf)[2], (bbf)[3]); \
    mma_bf16(accA,  (abf)[0][0], (abf)[0][1], (abf)[0][2], (abf)[0][3], (bbf)[0], (bbf)[1]); \
    mma_bf16(accB,  (abf)[0][0], (abf)[0][1], (abf)[0][2], (abf)[0][3], (bbf)[2], (bbf)[3]); \
    mma_bf16(accA2, (abf)[1][0], (abf)[1][1], (abf)[1][2], (abf)[1][3], (bbf)[0], (bbf)[1]); \
    mma_bf16(accB2, (abf)[1][0], (abf)[1][1], (abf)[1][2], (abf)[1][3], (bbf)[2], (bbf)[3]); \
} while (0)

// ================= HMMA bf16x3 GEMM 128x128, single-barrier 2-stage ==========
// EPI: 0 fp32 store, 2 split-bf16 store, 3 QKV-fused, 4 PV+diag+split
#define BM 128
#define BN 128
#define BK 32
#define A_ST 20
#define ASZ  (128 * A_ST)
#define BNT_ST 20
#define BNN_ST 68

template <bool NT, int EPI, bool TRUNC, bool LOWER>
__global__ __launch_bounds__(256, 2) void gemm_bf3(
    const bf16* __restrict__ Agb, const bf16* __restrict__ Ags, int lda, size_t sA,
    const bf16* __restrict__ Bgb, const bf16* __restrict__ Bgs, int ldb, size_t sB,
    float* __restrict__ Cf, float* __restrict__ Cf2,
    bf16* __restrict__ Cb, bf16* __restrict__ Cs,
    const bf16* __restrict__ Vb, const bf16* __restrict__ Vs,
    int ldc, size_t sC, int K, float alpha)
{
    const int bz = blockIdx.z;
    Agb += (size_t)bz * sA; Ags += (size_t)bz * sA;
    Bgb += (size_t)bz * sB; Bgs += (size_t)bz * sB;
    if (EPI == 2) { Cb += (size_t)bz * sC; Cs += (size_t)bz * sC; }
    else if (EPI == 0) { Cf += (size_t)bz * sC; }
    else if (EPI == 4) {
        Cb += (size_t)bz * sC; Cs += (size_t)bz * sC;
        Vb += (size_t)bz * sC; Vs += (size_t)bz * sC;
        Cf += (size_t)bz * S;   // pdiag per head
    }

    int bm, bn;
    if (LOWER) {
        int idx = blockIdx.x;
        int r = (int)((sqrtf(8.f * (float)idx + 1.f) - 1.f) * 0.5f);
        while ((r + 1) * (r + 2) / 2 <= idx) r++;
        while (r * (r + 1) / 2 > idx) r--;
        bm = r * BM;
        bn = (idx - r * (r + 1) / 2) * BN;
    } else if (TRUNC) {
        bm = (gridDim.y - 1 - blockIdx.y) * BM;
        bn = blockIdx.x * BN;
    } else {
        bm = blockIdx.y * BM;
        bn = blockIdx.x * BN;
    }

    const int tid  = threadIdx.x;
    const int wid  = tid >> 5;
    const int lane = tid & 31;
    const int g  = lane >> 2;
    const int tg = lane & 3;
    const int wm = (wid & 3) * 32;
    const int wn = (wid >> 2) * 64;

    extern __shared__ unsigned sm[];
    const unsigned smb = (unsigned)__cvta_generic_to_shared(sm);
    const int BSZ = NT ? (128 * BNT_ST) : (32 * BNN_ST);
    const int STG = 2 * ASZ + 2 * BSZ;
    const int OFF_AB = 0, OFF_AS = ASZ, OFF_BB = 2 * ASZ, OFF_BS = 2 * ASZ + BSZ;

    const int kend = TRUNC ? (bm + BM) : K;
    const int T = kend / BK;

    float acc[2][8][4];
#pragma unroll
    for (int i = 0; i < 2; i++)
#pragma unroll
        for (int j = 0; j < 8; j++)
#pragma unroll
            for (int t2 = 0; t2 < 4; t2++) acc[i][j][t2] = 0.f;

    const int a_row = (lane & 15);
    const int a_hi  = (lane >> 4) << 2;
    const int bnt_row = (lane & 7) + ((lane >> 4) & 1) * 8;
    const int bnt_hi  = ((lane >> 3) & 1) * 4;
    const int bnn_krow = (lane & 15);
    const int bnn_nhi  = ((lane >> 4) & 1) * 8;

    // prefetch tile 0
    {
        const int so = 0;
#pragma unroll
        for (int r = 0; r < 2; r++) {
            int s = tid + r * 256;
            int arow = s >> 2, aseg = s & 3;
            size_t aoff = (size_t)(bm + arow) * lda + aseg * 8;
            unsigned adst = smb + (so + OFF_AB + arow * A_ST + aseg * 4) * 4;
            cp16(adst, Agb + aoff);
            cp16(adst + ASZ * 4, Ags + aoff);
            if (NT) {
                size_t boff = (size_t)(bn + arow) * ldb + aseg * 8;
                unsigned bdst = smb + (so + OFF_BB + arow * BNT_ST + aseg * 4) * 4;
                cp16(bdst, Bgb + boff);
                cp16(bdst + BSZ * 4, Bgs + boff);
            } else {
                int krow = s >> 4, nseg = s & 15;
                size_t boff = (size_t)krow * ldb + bn + nseg * 8;
                unsigned bdst = smb + (so + OFF_BB + krow * BNN_ST + nseg * 4) * 4;
                cp16(bdst, Bgb + boff);
                cp16(bdst + BSZ * 4, Bgs + boff);
            }
        }
        cp_commit();
    }

    for (int t = 0; t < T; t++) {
        cp_wait0();
        __syncthreads();

        if (t + 1 < T) {
            const int so = ((t + 1) & 1) * STG;
            const int k0 = (t + 1) * BK;
#pragma unroll
            for (int r = 0; r < 2; r++) {
                int s = tid + r * 256;
                int arow = s >> 2, aseg = s & 3;
                size_t aoff = (size_t)(bm + arow) * lda + k0 + aseg * 8;
                unsigned adst = smb + (so + OFF_AB + arow * A_ST + aseg * 4) * 4;
                cp16(adst, Agb + aoff);
                cp16(adst + ASZ * 4, Ags + aoff);
                if (NT) {
                    size_t boff = (size_t)(bn + arow) * ldb + k0 + aseg * 8;
                    unsigned bdst = smb + (so + OFF_BB + arow * BNT_ST + aseg * 4) * 4;
                    cp16(bdst, Bgb + boff);
                    cp16(bdst + BSZ * 4, Bgs + boff);
                } else {
                    int krow = s >> 4, nseg = s & 15;
                    size_t boff = (size_t)(k0 + krow) * ldb + bn + nseg * 8;
                    unsigned bdst = smb + (so + OFF_BB + krow * BNN_ST + nseg * 4) * 4;
                    cp16(bdst, Bgb + boff);
                    cp16(bdst + BSZ * 4, Bgs + boff);
                }
            }
            cp_commit();
        }

        const int so = (t & 1) * STG;
#pragma unroll
        for (int kk = 0; kk < 2; kk++) {
            unsigned ab[2][4], as_[2][4];
#pragma unroll
            for (int mi = 0; mi < 2; mi++) {
                int idx = (wm + mi * 16 + a_row) * A_ST + kk * 8 + a_hi;
                ldsm_x4(ab[mi],  smb + (so + OFF_AB + idx) * 4);
                ldsm_x4(as_[mi], smb + (so + OFF_AS + idx) * 4);
            }
#pragma unroll
            for (int nj = 0; nj < 4; nj++) {
                unsigned bb[4], bs[4];
                if (NT) {
                    int idx = (wn + nj * 16 + bnt_row) * BNT_ST + kk * 8 + bnt_hi;
                    ldsm_x4(bb, smb + (so + OFF_BB + idx) * 4);
                    ldsm_x4(bs, smb + (so + OFF_BS + idx) * 4);
                } else {
                    int idx = (kk * 16 + bnn_krow) * BNN_ST + ((wn + nj * 16 + bnn_nhi) >> 1);
                    ldsm_x4t(bb, smb + (so + OFF_BB + idx) * 4);
                    ldsm_x4t(bs, smb + (so + OFF_BS + idx) * 4);
                }
                MMA_NJ_BLOCK(acc[0][2 * nj], acc[0][2 * nj + 1],
                             acc[1][2 * nj], acc[1][2 * nj + 1], ab, as_, bb, bs);
            }
        }
    }

    const bool split_out = (EPI == 2) || (EPI == 4) || (EPI == 3 && bz == 2);
    float* fout = (EPI == 3) ? ((bz == 1) ? Cf2 : Cf) : Cf;

#pragma unroll
    for (int mi = 0; mi < 2; mi++) {
#pragma unroll
        for (int ni = 0; ni < 8; ni++) {
            int r0 = bm + wm + mi * 16 + g;
            int c0 = bn + wn + ni * 8 + tg * 2;
            float v0 = acc[mi][ni][0] * alpha;
            float v1 = acc[mi][ni][1] * alpha;
            float v2 = acc[mi][ni][2] * alpha;
            float v3 = acc[mi][ni][3] * alpha;
            if (EPI == 4) {
                // fused diagonal term: out += pdiag[q] * (vb + vs)
                size_t e0 = (size_t)r0 * ldc + c0;
                size_t e1 = (size_t)(r0 + 8) * ldc + c0;
                float pd0 = Cf[r0];
                float pd1 = Cf[r0 + 8];
                v0 += pd0 * (__bfloat162float(Vb[e0])     + __bfloat162float(Vs[e0]));
                v1 += pd0 * (__bfloat162float(Vb[e0 + 1]) + __bfloat162float(Vs[e0 + 1]));
                v2 += pd1 * (__bfloat162float(Vb[e1])     + __bfloat162float(Vs[e1]));
                v3 += pd1 * (__bfloat162float(Vb[e1 + 1]) + __bfloat162float(Vs[e1 + 1]));
            }
            if (split_out) {
                bf16 b0 = __float2bfloat16(v0), b1 = __float2bfloat16(v1);
                bf16 b2 = __float2bfloat16(v2), b3 = __float2bfloat16(v3);
                __nv_bfloat162 pb0, pb1, ps0, ps1;
                pb0.x = b0; pb0.y = b1; pb1.x = b2; pb1.y = b3;
                ps0.x = __float2bfloat16(v0 - __bfloat162float(b0));
                ps0.y = __float2bfloat16(v1 - __bfloat162float(b1));
                ps1.x = __float2bfloat16(v2 - __bfloat162float(b2));
                ps1.y = __float2bfloat16(v3 - __bfloat162float(b3));
                *(__nv_bfloat162*)(Cb + (size_t)r0 * ldc + c0)       = pb0;
                *(__nv_bfloat162*)(Cb + (size_t)(r0 + 8) * ldc + c0) = pb1;
                *(__nv_bfloat162*)(Cs + (size_t)r0 * ldc + c0)       = ps0;
                *(__nv_bfloat162*)(Cs + (size_t)(r0 + 8) * ldc + c0) = ps1;
            } else {
                *(float2*)(fout + (size_t)r0 * ldc + c0)       = make_float2(v0, v1);
                *(float2*)(fout + (size_t)(r0 + 8) * ldc + c0) = make_float2(v2, v3);
            }
        }
    }
}

// ---------------- split fp32 -> bf16 big/small --------------------------------
__device__ __forceinline__ void split4(const float4 v, bf16* xb, bf16* xs, size_t i)
{
    bf16 b0 = __float2bfloat16(v.x), b1 = __float2bfloat16(v.y);
    bf16 b2 = __float2bfloat16(v.z), b3 = __float2bfloat16(v.w);
    __nv_bfloat162 pb0, pb1, ps0, ps1;
    pb0.x = b0; pb0.y = b1; pb1.x = b2; pb1.y = b3;
    ps0.x = __float2bfloat16(v.x - __bfloat162float(b0));
    ps0.y = __float2bfloat16(v.y - __bfloat162float(b1));
    ps1.x = __float2bfloat16(v.z - __bfloat162float(b2));
    ps1.y = __float2bfloat16(v.w - __bfloat162float(b3));
    *(__nv_bfloat162*)(xb + i)     = pb0;
    *(__nv_bfloat162*)(xb + i + 2) = pb1;
    *(__nv_bfloat162*)(xs + i)     = ps0;
    *(__nv_bfloat162*)(xs + i + 2) = ps1;
}

__global__ void split_kernel(const float* __restrict__ x,
                             bf16* __restrict__ xb, bf16* __restrict__ xs)
{
    size_t i = ((size_t)blockIdx.x * 256 + threadIdx.x) * 8;
    float4 v0 = *(const float4*)(x + i);
    float4 v1 = *(const float4*)(x + i + 4);
    split4(v0, xb, xs, i);
    split4(v1, xb, xs, i + 4);
}

__global__ void splitw_kernel(const float* __restrict__ W0, const float* __restrict__ W1,
                              const float* __restrict__ W2, const float* __restrict__ W3,
                              bf16* __restrict__ xb, bf16* __restrict__ xs)
{
    int w = blockIdx.y;
    const float* x = (w == 0) ? W0 : (w == 1) ? W1 : (w == 2) ? W2 : W3;
    size_t base = (size_t)w * HID * HID;
    size_t i = ((size_t)blockIdx.x * 256 + threadIdx.x) * 8;
    float4 v0 = *(const float4*)(x + i);
    float4 v1 = *(const float4*)(x + i + 4);
    split4(v0, xb + base, xs + base, i);
    split4(v1, xb + base, xs + base, i + 4);
}

// ---------------- MsPoE rotary -> split bf16 ----------------------------------
__global__ void rope_split_kernel(const float* __restrict__ q, const float* __restrict__ k,
                                  const int* __restrict__ pos_ids,
                                  bf16* __restrict__ qb, bf16* __restrict__ qs,
                                  bf16* __restrict__ kb, bf16* __restrict__ ks)
{
    int i = blockIdx.x * blockDim.x + threadIdx.x;
    int d = i & 63;
    int h = (i >> 6) & 31;
    int s = i >> 11;
    float ratio = 1.2f + (0.6f / 31.0f) * (float)h;
    float t = (float)pos_ids[s] / ratio;
    float inv_freq = exp2f(-(float)d * (13.287712379549449f / 64.0f));
    float f = t * inv_freq;
    float c, sn;
    sincosf(f, &sn, &c);
    size_t base = (size_t)s * HID + h * HD + d;

    float x1 = q[base], x2 = q[base + 64];
    float y0 = x1 * c - x2 * sn;
    float y1 = x2 * c + x1 * sn;
    bf16 t0 = __float2bfloat16(y0);
    bf16 t1 = __float2bfloat16(y1);
    qb[base] = t0;
    qs[base] = __float2bfloat16(y0 - __bfloat162float(t0));
    qb[base + 64] = t1;
    qs[base + 64] = __float2bfloat16(y1 - __bfloat162float(t1));

    x1 = k[base]; x2 = k[base + 64];
    y0 = x1 * c - x2 * sn;
    y1 = x2 * c + x1 * sn;
    t0 = __float2bfloat16(y0);
    t1 = __float2bfloat16(y1);
    kb[base] = t0;
    ks[base] = __float2bfloat16(y0 - __bfloat162float(t0));
    kb[base + 64] = t1;
    ks[base + 64] = __float2bfloat16(y1 - __bfloat162float(t1));
}

// ---------------- probs1: in-place softmax over k<=q ---------------------------
__global__ void probs1_kernel(float* __restrict__ scores)
{
    int q = blockIdx.x, h = blockIdx.y;
    float* row = scores + ((size_t)h * S + q) * S;
    __shared__ float red[256];
    int tid = threadIdx.x;

    float v[8];
    float m = -INFINITY;
#pragma unroll
    for (int j = 0; j < 8; j++) {
        int k = tid + j * 256;
        v[j] = (k <= q) ? row[k] : -INFINITY;
        m = fmaxf(m, v[j]);
    }
    red[tid] = m;
    __syncthreads();
    for (int st = 128; st; st >>= 1) {
        if (tid < st) red[tid] = fmaxf(red[tid], red[tid + st]);
        __syncthreads();
    }
    m = red[0];
    __syncthreads();

    float sum = 0.f;
#pragma unroll
    for (int j = 0; j < 8; j++) {
        v[j] = (v[j] > -INFINITY) ? __expf(v[j] - m) : 0.f;
        sum += v[j];
    }
    red[tid] = sum;
    __syncthreads();
    for (int st = 128; st; st >>= 1) {
        if (tid < st) red[tid] += red[tid + st];
        __syncthreads();
    }
    float inv = 1.0f / red[0];
#pragma unroll
    for (int j = 0; j < 8; j++) {
        int k = tid + j * 256;
        if (k <= q) row[k] = v[j] * inv;
    }
}

// ---------------- hh partial sums over q-chunks --------------------------------
__global__ void hh_part_kernel(const float* __restrict__ p1, float* __restrict__ part)
{
    int kb = blockIdx.x, qc = blockIdx.y, h = blockIdx.z;
    if (qc < kb) return;
    int k = kb * 256 + threadIdx.x;
    const float* base = p1 + (size_t)h * S * S;
    int q0 = qc * 256;
    float acc = 0.f;
    for (int q = q0; q < q0 + 256; q++) {
        if (q >= k) acc += base[(size_t)q * S + k];
    }
    part[((size_t)qc * NH + h) * S + k] = acc;
}

__global__ void hh_reduce_kernel(const float* __restrict__ part, float* __restrict__ hh)
{
    int h = blockIdx.y;
    int k = blockIdx.x * 256 + threadIdx.x;
    int kb = k >> 8;
    float acc = 0.f;
    for (int qc = kb; qc < 8; qc++)
        acc += part[((size_t)qc * NH + h) * S + k];
    hh[h * S + k] = acc;
}

// ---------------- top-204 via histogram pruning + warp selection ----------------
__global__ void topk_mask_kernel(const float* __restrict__ hh, float* __restrict__ mask)
{
    int h = blockIdx.x, tid = threadIdx.x;
    __shared__ float cv[SEL];
    __shared__ int   ci[SEL];
    __shared__ unsigned hist[2048];
    __shared__ int cand_n, thrbin;

    for (int i = tid; i < 2048; i += 256) hist[i] = 0;
    for (int k = tid; k < S; k += 256) mask[h * S + k] = (k >= SEL) ? 0.f : NEGV;
    if (tid == 0) cand_n = 0;
    __syncthreads();

    for (int i = tid; i < SEL; i += 256) {
        unsigned b = __float_as_uint(hh[h * S + i]);
        atomicAdd(&hist[b >> 21], 1u);
    }
    __syncthreads();

    if (tid == 0) {
        unsigned c = 0;
        int b = 2047;
        for (; b > 0; b--) {
            c += hist[b];
            if (c >= HHSZ) break;
        }
        thrbin = b;
    }
    __syncthreads();
    int tb = thrbin;

    for (int i = tid; i < SEL; i += 256) {
        float v = hh[h * S + i];
        if ((int)(__float_as_uint(v) >> 21) >= tb) {
            int p = atomicAdd(&cand_n, 1);
            cv[p] = v;
            ci[p] = i;
        }
    }
    __syncthreads();
    int n = cand_n;

    if (tid < 32) {
        for (int it = 0; it < HHSZ; it++) {
            float bm = -INFINITY;
            int bi = 1 << 30;
            for (int j = tid; j < n; j += 32) {
                float v = cv[j];
                int oi = ci[j];
                if (v > bm || (v == bm && oi < bi)) { bm = v; bi = oi; }
            }
#pragma unroll
            for (int off = 16; off; off >>= 1) {
                float ov = __shfl_down_sync(0xffffffffu, bm, off);
                int   oi = __shfl_down_sync(0xffffffffu, bi, off);
                if (ov > bm || (ov == bm && oi < bi)) { bm = ov; bi = oi; }
            }
            bi = __shfl_sync(0xffffffffu, bi, 0);
            if (tid == 0) mask[h * S + bi] = 0.f;
            for (int j = tid; j < n; j += 32)
                if (ci[j] == bi) cv[j] = -INFINITY;
            __syncwarp();
        }
    }
}

// ---------------- fused: collect kept indices + gather compacted V --------------
__global__ void collect_gather_kernel(const float* __restrict__ mask, int* __restrict__ idx,
                                      const bf16* __restrict__ vb, const bf16* __restrict__ vs,
                                      bf16* __restrict__ vcb, bf16* __restrict__ vcs)
{
    int h = blockIdx.x, tid = threadIdx.x;
    __shared__ int cnt[256];
    __shared__ int sidx[NKP];
    int local[8];
    int c = 0;
#pragma unroll
    for (int i = 0; i < 8; i++) {
        int k = tid * 8 + i;
        if (mask[h * S + k] == 0.f) local[c++] = k;
    }
    cnt[tid] = c;
    __syncthreads();
    for (int off = 1; off < 256; off <<= 1) {
        int v = (tid >= off) ? cnt[tid - off] : 0;
        __syncthreads();
        cnt[tid] += v;
        __syncthreads();
    }
    int base = cnt[tid] - c;
    for (int j = 0; j < c; j++) sidx[base + j] = local[j];
    if (tid < NKP - NKEEP) sidx[NKEEP + tid] = -1;
    __syncthreads();

    // publish idx to global (softmax2 needs it)
    for (int j = tid; j < NKP; j += 256) idx[h * NKP + j] = sidx[j];

    // gather: NKP rows x 128 cols bf16, uint4 = 8 bf16 -> 16 chunks/row
    const int CHUNKS = NKP * (HD / 8);   // 6656
    uint4 zero4;
    zero4.x = 0u; zero4.y = 0u; zero4.z = 0u; zero4.w = 0u;
    for (int e = tid; e < CHUNKS; e += 256) {
        int j = e >> 4;
        int seg = e & 15;
        int i = sidx[j];
        size_t dst = ((size_t)h * NKP + j) * HD + seg * 8;
        if (i >= 0) {
            size_t src = (size_t)i * HID + h * HD + seg * 8;
            *(uint4*)(vcb + dst) = *(const uint4*)(vb + src);
            *(uint4*)(vcs + dst) = *(const uint4*)(vs + src);
        } else {
            *(uint4*)(vcb + dst) = zero4;
            *(uint4*)(vcs + dst) = zero4;
        }
    }
}

// ---------------- softmax2: renormalize + compact kept columns ------------------
__global__ void softmax2_compact_kernel(const float* __restrict__ p1,
                                        const float* __restrict__ mask,
                                        const int* __restrict__ idx,
                                        bf16* __restrict__ pcb, bf16* __restrict__ pcs,
                                        float* __restrict__ pdiag)
{
    int q = blockIdx.x, h = blockIdx.y, tid = threadIdx.x;
    const float* row = p1 + ((size_t)h * S + q) * S;
    __shared__ int sidx[NKP];
    __shared__ float red[256];
    for (int j = tid; j < NKP; j += 256) sidx[j] = idx[h * NKP + j];
    __syncthreads();

    float v[2];
    float sum = 0.f;
#pragma unroll
    for (int r = 0; r < 2; r++) {
        int j = tid + r * 256;
        float p = 0.f;
        if (j < NKP) {
            int ij = sidx[j];
            if (ij >= 0 && ij <= q) p = row[ij];
        }
        v[r] = p;
        sum += p;
    }
    bool kept_q = (mask[h * S + q] == 0.f);
    float pd = kept_q ? 0.f : row[q];

    red[tid] = sum;
    __syncthreads();
    for (int st = 128; st; st >>= 1) {
        if (tid < st) red[tid] += red[tid + st];
        __syncthreads();
    }
    float inv = 1.0f / (red[0] + pd);

    size_t off = ((size_t)h * S + q) * NKP;
#pragma unroll
    for (int r = 0; r < 2; r++) {
        int j = tid + r * 256;
        if (j < NKP) {
            float val = v[r] * inv;
            bf16 b = __float2bfloat16(val);
            pcb[off + j] = b;
            pcs[off + j] = __float2bfloat16(val - __bfloat162float(b));
        }
    }
    if (tid == 0) pdiag[h * S + q] = kept_q ? 0.f : pd * inv;
}

// ---------------- launch --------------------------------------------------------
extern "C" void kernel_launch(void* const* d_in, const int* in_sizes, int n_in,
                              void* d_out, int out_size)
{
    const float* hs = (const float*)d_in[0];
    const float* W0 = (const float*)d_in[1];
    const float* W1 = (const float*)d_in[2];
    const float* W2 = (const float*)d_in[3];
    const float* W3 = (const float*)d_in[4];
    const int* pos = (const int*)d_in[5];
    float* out = (float*)d_out;

    float *q, *k, *scores, *hh, *hhp, *mask, *pdiag;
    int* idx;
    bf16 *hsb, *hss, *wb, *ws, *qb, *qs, *kb, *ks, *vb, *vs;
    bf16 *pcb, *pcs, *vcb, *vcs, *ab, *as;
    cudaGetSymbolAddress((void**)&q, g_q);
    cudaGetSymbolAddress((void**)&k, g_k);
    cudaGetSymbolAddress((void**)&scores, g_scores);
    cudaGetSymbolAddress((void**)&hh, g_hh);
    cudaGetSymbolAddress((void**)&hhp, g_hhpart);
    cudaGetSymbolAddress((void**)&mask, g_mask);
    cudaGetSymbolAddress((void**)&pdiag, g_pdiag);
    cudaGetSymbolAddress((void**)&idx, g_idx);
    cudaGetSymbolAddress((void**)&hsb, g_hs_b);
    cudaGetSymbolAddress((void**)&hss, g_hs_s);
    cudaGetSymbolAddress((void**)&wb, g_w_b);
    cudaGetSymbolAddress((void**)&ws, g_w_s);
    cudaGetSymbolAddress((void**)&qb, g_qb);
    cudaGetSymbolAddress((void**)&qs, g_qs);
    cudaGetSymbolAddress((void**)&kb, g_kb);
    cudaGetSymbolAddress((void**)&ks, g_ks);
    cudaGetSymbolAddress((void**)&vb, g_vb);
    cudaGetSymbolAddress((void**)&vs, g_vs);
    cudaGetSymbolAddress((void**)&pcb, g_pcb);
    cudaGetSymbolAddress((void**)&pcs, g_pcs);
    cudaGetSymbolAddress((void**)&vcb, g_vcb);
    cudaGetSymbolAddress((void**)&vcs, g_vcs);
    cudaGetSymbolAddress((void**)&ab, g_ab);
    cudaGetSymbolAddress((void**)&as, g_as);

    const int SM_NT = (2 * (2 * ASZ + 2 * 128 * BNT_ST)) * 4;
    const int SM_NN = (2 * (2 * ASZ + 2 * 32 * BNN_ST)) * 4;
    cudaFuncSetAttribute(gemm_bf3<true, 3, false, false>, cudaFuncAttributeMaxDynamicSharedMemorySize, SM_NT);
    cudaFuncSetAttribute(gemm_bf3<true, 0, false, false>, cudaFuncAttributeMaxDynamicSharedMemorySize, SM_NT);
    cudaFuncSetAttribute(gemm_bf3<true, 0, false, true>,  cudaFuncAttributeMaxDynamicSharedMemorySize, SM_NT);
    cudaFuncSetAttribute(gemm_bf3<false, 4, false, false>, cudaFuncAttributeMaxDynamicSharedMemorySize, SM_NN);

    split_kernel<<<(S * HID) / 2048, 256>>>(hs, hsb, hss);
    splitw_kernel<<<dim3((HID * HID) / 2048, 4), 256>>>(W0, W1, W2, W3, wb, ws);

    // fused Q/K/V projections
    dim3 gqkv(HID / BN, S / BM, 3);
    gemm_bf3<true, 3, false, false><<<gqkv, 256, SM_NT>>>(
        hsb, hss, HID, 0, wb, ws, HID, (size_t)HID * HID,
        q, k, vb, vs, (bf16*)0, (bf16*)0, HID, 0, HID, 1.f);

    rope_split_kernel<<<(S * NH * 64) / 256, 256>>>(q, k, pos, qb, qs, kb, ks);

    // QK^T lower-triangle tiles only
    dim3 gs(136, 1, NH);
    gemm_bf3<true, 0, false, true><<<gs, 256, SM_NT>>>(
        qb, qs, HID, (size_t)HD, kb, ks, HID, (size_t)HD,
        scores, (float*)0, (bf16*)0, (bf16*)0, (bf16*)0, (bf16*)0,
        S, (size_t)S * S, HD, 0.08838834764831845f);

    probs1_kernel<<<dim3(S, NH), 256>>>(scores);
    hh_part_kernel<<<dim3(8, 8, NH), 256>>>(scores, hhp);
    hh_reduce_kernel<<<dim3(8, NH), 256>>>(hhp, hh);
    topk_mask_kernel<<<NH, 256>>>(hh, mask);

    // sparse PV path: fused collect+gather, compact probs
    collect_gather_kernel<<<NH, 256>>>(mask, idx, vb, vs, vcb, vcs);
    softmax2_compact_kernel<<<dim3(S, NH), 256>>>(scores, mask, idx, pcb, pcs, pdiag);

    // PV with fused diagonal + split epilogue (EPI=4)
    dim3 gpv(1, S / BM, NH);
    gemm_bf3<false, 4, false, false><<<gpv, 256, SM_NN>>>(
        pcb, pcs, NKP, (size_t)S * NKP, vcb, vcs, HD, (size_t)NKP * HD,
        pdiag, (float*)0, ab, as, vb, vs, HID, (size_t)HD, NKP, 1.f);

    // O projection
    gemm_bf3<true, 0, false, false><<<dim3(HID / BN, S / BM, 1), 256, SM_NT>>>(
        ab, as, HID, 0, wb + 3 * (size_t)HID * HID, ws + 3 * (size_t)HID * HID, HID, 0,
        out, (float*)0, (bf16*)0, (bf16*)0, (bf16*)0, (bf16*)0, HID, 0, HID, 1.f);
}